// round 1
// baseline (speedup 1.0000x reference)
#include <cuda_runtime.h>
#include <cstdint>
#include <math.h>

// Problem constants (fixed by the dataset)
#define NUM_GRAPHS   8
#define M_NODES      4096
#define N_TOTAL      32768
#define KNN          50
#define NK_          (N_TOTAL * KNN)      // 1,638,400 directed knn edges
#define E_           (2 * NK_)            // 3,276,800 total edges (undirected doubled)
#define CAP          320                  // survivor buffer per node
#define NPW          8                    // nodes per warp
#define WPB          8                    // warps per block
#define NPB          (NPW * WPB)          // 64 nodes per block
#define THREADS      256
#define NBLOCKS      (N_TOTAL / NPB)      // 512
#define SMEM_BYTES   (M_NODES * 16 + WPB * CAP * 8)   // 65536 + 20480 = 86016

// Global scratch for survivor keys (no cudaMalloc allowed)
__device__ unsigned long long g_knn_scratch[(size_t)N_TOTAL * CAP];

__device__ __forceinline__ unsigned int f2ord(float f) {
    // monotone float -> uint mapping (handles tiny negative d2 from rounding)
    unsigned int b = __float_as_uint(f);
    unsigned int m = ((unsigned int)((int)b >> 31)) | 0x80000000u;
    return b ^ m;
}

extern "C" __global__ void __launch_bounds__(THREADS)
knn_rdf_kernel(const float* __restrict__ pos, float* __restrict__ out)
{
    extern __shared__ unsigned char smem_raw[];
    float4* spos = (float4*)smem_raw;                                        // [M_NODES]
    unsigned long long* skey = (unsigned long long*)(smem_raw + M_NODES * 16); // [WPB*CAP]

    const int g        = blockIdx.x / (M_NODES / NPB);
    const int chunk    = blockIdx.x % (M_NODES / NPB);
    const int nodeBase = chunk * NPB;
    const float* gp    = pos + (size_t)g * M_NODES * 3;

    // ---- load graph positions into smem as (x,y,z,|p|^2) ----
    for (int t = threadIdx.x; t < M_NODES; t += THREADS) {
        float x = gp[t * 3 + 0];
        float y = gp[t * 3 + 1];
        float z = gp[t * 3 + 2];
        float sq = x * x + y * y + z * z;   // same formula/order as reference sum(p*p)
        spos[t] = make_float4(x, y, z, sq);
    }
    __syncthreads();

    const int wid  = threadIdx.x >> 5;
    const int lane = threadIdx.x & 31;
    const int myBase = nodeBase + wid * NPW;
    const unsigned lmask = (1u << lane) - 1u;
    const float INF_F = __int_as_float(0x7f800000);

    // node coordinates in registers (replicated across lanes)
    float nx[NPW], ny[NPW], nz[NPW], nsq[NPW];
#pragma unroll
    for (int n = 0; n < NPW; n++) {
        float4 p = spos[myBase + n];
        nx[n] = p.x; ny[n] = p.y; nz[n] = p.z; nsq[n] = p.w;
    }

    // ---------- Phase 1: per-node threshold from a 512-candidate sample ----------
    // T = 12th smallest sampled d2  (expected full rank ~96 -> survivors ~50..200)
    float Tn[NPW];
#pragma unroll
    for (int n = 0; n < NPW; n++) {
        const int iloc = myBase + n;
        float v[16];
#pragma unroll
        for (int s = 0; s < 16; s++) {
            int j = lane + s * 32;                 // indices are i.i.d. random positions
            float4 pj = spos[j];
            float dot = nx[n] * pj.x + ny[n] * pj.y + nz[n] * pj.z;
            float d2 = (nsq[n] + pj.w) - 2.0f * dot;
            v[s] = (j == iloc) ? INF_F : d2;
        }
        float lmin = v[0];
#pragma unroll
        for (int s = 1; s < 16; s++) lmin = fminf(lmin, v[s]);
        int popped = 0;
        float wmin;
        while (true) {
            wmin = lmin;
#pragma unroll
            for (int off = 16; off; off >>= 1)
                wmin = fminf(wmin, __shfl_xor_sync(0xffffffffu, wmin, off));
            unsigned bal = __ballot_sync(0xffffffffu, lmin == wmin);
            popped += __popc(bal);
            if (popped >= 12) break;
            if (lmin == wmin) {
                bool done = false;
#pragma unroll
                for (int s = 0; s < 16; s++) {
                    if (!done && v[s] == wmin) { v[s] = INF_F; done = true; }
                }
                lmin = v[0];
#pragma unroll
                for (int s = 1; s < 16; s++) lmin = fminf(lmin, v[s]);
            }
        }
        Tn[n] = wmin;
    }

    // ---------- Phase 2: full scan, compact survivors (d2 <= T) ----------
    unsigned cnt[NPW];
    unsigned sbase[NPW];
#pragma unroll
    for (int n = 0; n < NPW; n++) {
        cnt[n] = 0;
        sbase[n] = (unsigned)(g * M_NODES + myBase + n) * CAP;
    }

    for (int it = 0; it < M_NODES / 32; it++) {
        int j = lane + it * 32;
        float4 pj = spos[j];
#pragma unroll
        for (int n = 0; n < NPW; n++) {
            float dot = nx[n] * pj.x + ny[n] * pj.y + nz[n] * pj.z;
            float d2 = (nsq[n] + pj.w) - 2.0f * dot;   // exact same identity as reference
            bool p = (d2 <= Tn[n]) && (j != (myBase + n));
            unsigned bal = __ballot_sync(0xffffffffu, p);
            if (p) {
                unsigned slot = cnt[n] + (unsigned)__popc(bal & lmask);
                if (slot < CAP)
                    g_knn_scratch[sbase[n] + slot] =
                        ((unsigned long long)f2ord(d2) << 32) | (unsigned)j;
            }
            cnt[n] += (unsigned)__popc(bal);
        }
    }

    // single-node rescan used by the (rare) threshold-retry path
    auto scan_one = [&](int ilocal, float px, float py, float pz, float psq,
                        float t, unsigned sb) -> int {
        int S = 0;
        for (int it = 0; it < M_NODES / 32; it++) {
            int j = lane + it * 32;
            float4 pj = spos[j];
            float dot = px * pj.x + py * pj.y + pz * pj.z;
            float d2 = (psq + pj.w) - 2.0f * dot;
            bool p = (d2 <= t) && (j != ilocal);
            unsigned bal = __ballot_sync(0xffffffffu, p);
            if (p) {
                int slot = S + __popc(bal & lmask);
                if (slot < CAP)
                    g_knn_scratch[sb + slot] =
                        ((unsigned long long)f2ord(d2) << 32) | (unsigned)j;
            }
            S += __popc(bal);
        }
        return S;
    };

    // ---------- Phase 3: retry loop (warp-uniform, rarely taken) ----------
#pragma unroll
    for (int n = 0; n < NPW; n++) {
        int S = (int)cnt[n];
        if (S < KNN || S > CAP) {
            float lo = 0.0f, hi = 0.0f;
            bool hasHi = false;
            float t = Tn[n];
            for (int iter = 0; iter < 200 && (S < KNN || S > CAP); iter++) {
                if (S < KNN) { lo = t; t = hasHi ? 0.5f * (lo + hi) : fmaxf(t * 2.0f, 1e-6f); }
                else         { hi = t; hasHi = true; t = 0.5f * (lo + hi); }
                S = scan_one(myBase + n, nx[n], ny[n], nz[n], nsq[n], t, sbase[n]);
            }
            cnt[n] = (unsigned)S;
        }
    }

    __threadfence_block();   // make this warp's scratch stores visible to its own loads

    // ---------- Phase 4: exact ranking of survivors + output ----------
    auto rank_out = [&](int ilocal, int S, unsigned sb) {
        unsigned long long* kb = skey + (size_t)wid * CAP;
        __syncwarp();
        for (int q = lane; q < S; q += 32) kb[q] = g_knn_scratch[sb + q];
        __syncwarp();
        float4 pi = spos[ilocal];
        int ig = g * M_NODES + ilocal;
        int cmax = (S + 31) >> 5;
        for (int c = 0; c < cmax; c++) {
            int o = c * 32 + lane;
            bool act = o < S;
            unsigned long long mk = act ? kb[o] : 0xFFFFFFFFFFFFFFFFull;
            int rank = 0;
            for (int q = 0; q < S; q++) rank += (kb[q] < mk) ? 1 : 0;   // keys unique
            if (act && rank < KNN) {
                int j = (int)(unsigned)(mk & 0xFFFFFFFFull);
                float4 pj = spos[j];
                // reference Distance transform: direct difference formula
                float dx = pj.x - pi.x, dy = pj.y - pi.y, dz = pj.z - pi.z;
                float dist = sqrtf(dx * dx + dy * dy + dz * dz);
                int jg = g * M_NODES + j;
                size_t e1 = (size_t)ig * KNN + (size_t)rank;
                size_t e2 = (size_t)NK_ + e1;
                // edge_index rows: [src|dst] , [dst|src]
                out[e1] = (float)jg;
                out[(size_t)E_ + e1] = (float)ig;
                out[e2] = (float)ig;
                out[(size_t)E_ + e2] = (float)jg;
                // dist
                out[2 * (size_t)E_ + e1] = dist;
                out[2 * (size_t)E_ + e2] = dist;
                // RDF: centers {0,2.5,5,7.5,10}, 2*w*w = 12.5
                size_t a1 = 3 * (size_t)E_ + e1 * 5;
                size_t a2 = 3 * (size_t)E_ + e2 * 5;
#pragma unroll
                for (int b = 0; b < 5; b++) {
                    float tt = dist - 2.5f * (float)b;
                    float av = expf(-((tt * tt) / 12.5f));
                    out[a1 + b] = av;
                    out[a2 + b] = av;
                }
            }
        }
        __syncwarp();
    };

#pragma unroll
    for (int n = 0; n < NPW; n++) {
        rank_out(myBase + n, (int)cnt[n], sbase[n]);
    }
}

extern "C" void kernel_launch(void* const* d_in, const int* in_sizes, int n_in,
                              void* d_out, int out_size)
{
    const float* pos = (const float*)d_in[0];   // [32768, 3] float32
    // d_in[1] = batch (int64, structure known), d_in[2] = num_graphs : unused
    float* out = (float*)d_out;                 // [8*E_] float32 concat of outputs

    cudaFuncSetAttribute(knn_rdf_kernel,
                         cudaFuncAttributeMaxDynamicSharedMemorySize, SMEM_BYTES);
    knn_rdf_kernel<<<NBLOCKS, THREADS, SMEM_BYTES>>>(pos, out);
}

// round 2
// speedup vs baseline: 1.5580x; 1.5580x over previous
#include <cuda_runtime.h>
#include <cstdint>
#include <math.h>

// Problem constants (fixed by the dataset)
#define NUM_GRAPHS   8
#define M_NODES      4096
#define N_TOTAL      32768
#define KNN          50
#define NK_          (N_TOTAL * KNN)      // 1,638,400 directed knn edges
#define E_           (2 * NK_)            // 3,276,800 total edges
#define CAP          256                  // survivor buffer per node
#define NPW          8                    // nodes per warp
#define WPB          8                    // warps per block
#define NPB          (NPW * WPB)          // 64 nodes per block
#define THREADS      256
#define NBLOCKS      (N_TOTAL / NPB)      // 512
#define TARGET_CNT   90.0f                // desired survivor count
#define SMEM_BYTES   (M_NODES * 16 + WPB * CAP * 8)   // 65536 + 16384 = 81920

// Global scratch for survivor keys (no cudaMalloc allowed)
__device__ unsigned long long g_knn_scratch[(size_t)N_TOTAL * CAP];

__device__ __forceinline__ unsigned int f2ord(float f) {
    unsigned int b = __float_as_uint(f);
    unsigned int m = ((unsigned int)((int)b >> 31)) | 0x80000000u;
    return b ^ m;
}
__device__ __forceinline__ float ord2f(unsigned int o) {
    unsigned int b = (o & 0x80000000u) ? (o ^ 0x80000000u) : ~o;
    return __uint_as_float(b);
}

extern "C" __global__ void __launch_bounds__(THREADS, 2)
knn_rdf_kernel(const float* __restrict__ pos, float* __restrict__ out)
{
    extern __shared__ unsigned char smem_raw[];
    float4* spos = (float4*)smem_raw;                                          // [M_NODES]
    unsigned long long* skey = (unsigned long long*)(smem_raw + M_NODES * 16); // [WPB*CAP]
    __shared__ int scnt[NPB];   // per-node survivor counters (each warp owns its 8)

    const int g        = blockIdx.x / (M_NODES / NPB);
    const int chunk    = blockIdx.x % (M_NODES / NPB);
    const int nodeBase = chunk * NPB;
    const float* gp    = pos + (size_t)g * M_NODES * 3;

    // ---- load graph positions into smem as (x,y,z,|p|^2) ----
    for (int t = threadIdx.x; t < M_NODES; t += THREADS) {
        float x = gp[t * 3 + 0];
        float y = gp[t * 3 + 1];
        float z = gp[t * 3 + 2];
        float sq = x * x + y * y + z * z;   // same as reference sum(p*p)
        spos[t] = make_float4(x, y, z, sq);
    }
    __syncthreads();

    const int wid  = threadIdx.x >> 5;
    const int lane = threadIdx.x & 31;
    const int myBase = nodeBase + wid * NPW;
    const unsigned lmask = (1u << lane) - 1u;

    if (lane < NPW) scnt[wid * NPW + lane] = 0;
    __syncwarp();

    // node coordinates in registers (replicated across lanes)
    float nx[NPW], ny[NPW], nz[NPW], nsq[NPW];
#pragma unroll
    for (int n = 0; n < NPW; n++) {
        float4 p = spos[myBase + n];
        nx[n] = p.x; ny[n] = p.y; nz[n] = p.z; nsq[n] = p.w;
    }

    // ---------- Phase 1: per-node threshold via density calibration ----------
    // min of 512-sample -> power-law scale (count ~ r^3 = (d2)^{3/2}) -> 2 count passes
    float Tn[NPW];
#pragma unroll
    for (int n = 0; n < NPW; n++) {
        const int iloc = myBase + n;
        unsigned lmino = 0xFFFFFFFFu;
#pragma unroll
        for (int s = 0; s < 16; s++) {
            int j = lane + s * 32;
            float4 pj = spos[j];
            float dot = nx[n] * pj.x + ny[n] * pj.y + nz[n] * pj.z;
            float d2 = (nsq[n] + pj.w) - 2.0f * dot;
            unsigned o = f2ord(d2);
            if (j != iloc) lmino = min(lmino, o);
        }
        unsigned mo = __reduce_min_sync(0xffffffffu, lmino);
        float m = fmaxf(ord2f(mo), 1e-7f);
        // min of 512 sample ~ full-graph count 8 -> scale to TARGET_CNT=90: (90/8)^(2/3)=5.0
        float T = m * 5.0f;

#pragma unroll
        for (int pass = 0; pass < 2; pass++) {
            int c = 0;
#pragma unroll
            for (int s = 0; s < 16; s++) {
                int j = lane + s * 32;
                float4 pj = spos[j];
                float dot = nx[n] * pj.x + ny[n] * pj.y + nz[n] * pj.z;
                float d2 = (nsq[n] + pj.w) - 2.0f * dot;
                c += (j != iloc && d2 <= T) ? 1 : 0;
            }
            int cs = __reduce_add_sync(0xffffffffu, c);
            float est = (float)cs * 8.0f;     // sample is 1/8 of graph
            float f = __powf(TARGET_CNT / fmaxf(est, 2.0f), 0.6666667f);
            f = fminf(fmaxf(f, 0.25f), 8.0f);
            T = T * f;
        }
        Tn[n] = T;
    }

    // ---------- Phase 2: full scan, atomic-compact survivors (d2 <= T) ----------
    unsigned sbase[NPW];
#pragma unroll
    for (int n = 0; n < NPW; n++)
        sbase[n] = (unsigned)(g * M_NODES + myBase + n) * CAP;

    for (int it = 0; it < M_NODES / 32; it++) {
        int j = lane + it * 32;
        float4 pj = spos[j];
#pragma unroll
        for (int n = 0; n < NPW; n++) {
            float dot = nx[n] * pj.x + ny[n] * pj.y + nz[n] * pj.z;
            float d2 = (nsq[n] + pj.w) - 2.0f * dot;   // same identity as reference
            if (d2 <= Tn[n] && j != (myBase + n)) {
                int slot = atomicAdd(&scnt[wid * NPW + n], 1);
                if (slot < CAP)
                    g_knn_scratch[sbase[n] + slot] =
                        ((unsigned long long)f2ord(d2) << 32) | (unsigned)j;
            }
        }
    }
    __syncwarp();

    unsigned cnt[NPW];
#pragma unroll
    for (int n = 0; n < NPW; n++) cnt[n] = (unsigned)scnt[wid * NPW + n];

    // ---------- Phase 3: retry (rare): bisect with count-only scans ----------
    // count-only full scan for one node
    auto count_one = [&](int ilocal, float px, float py, float pz, float psq,
                         float t) -> int {
        int c = 0;
        for (int it = 0; it < M_NODES / 32; it++) {
            int j = lane + it * 32;
            float4 pj = spos[j];
            float dot = px * pj.x + py * pj.y + pz * pj.z;
            float d2 = (psq + pj.w) - 2.0f * dot;
            c += (d2 <= t && j != ilocal) ? 1 : 0;
        }
        return __reduce_add_sync(0xffffffffu, c);
    };
    // compacting full scan (ballot-prefix, deterministic) for one node
    auto compact_one = [&](int ilocal, float px, float py, float pz, float psq,
                           float t, unsigned sb) -> int {
        int S = 0;
        for (int it = 0; it < M_NODES / 32; it++) {
            int j = lane + it * 32;
            float4 pj = spos[j];
            float dot = px * pj.x + py * pj.y + pz * pj.z;
            float d2 = (psq + pj.w) - 2.0f * dot;
            bool p = (d2 <= t) && (j != ilocal);
            unsigned bal = __ballot_sync(0xffffffffu, p);
            if (p) {
                int slot = S + __popc(bal & lmask);
                if (slot < CAP)
                    g_knn_scratch[sb + slot] =
                        ((unsigned long long)f2ord(d2) << 32) | (unsigned)j;
            }
            S += __popc(bal);
        }
        return S;
    };

#pragma unroll
    for (int n = 0; n < NPW; n++) {
        int S = (int)cnt[n];
        if (S < KNN || S > CAP) {
            float t = Tn[n];
            float lo = 0.0f, hi = 0.0f;
            bool hasHi = false;
            int c = S;
            for (int iter = 0; iter < 64 && (c < KNN || c > CAP); iter++) {
                if (c < KNN) { lo = t; t = hasHi ? 0.5f * (lo + hi) : fmaxf(t * 2.0f, 1e-6f); }
                else         { hi = t; hasHi = true; t = 0.5f * (lo + hi); }
                c = count_one(myBase + n, nx[n], ny[n], nz[n], nsq[n], t);
            }
            S = compact_one(myBase + n, nx[n], ny[n], nz[n], nsq[n], t, sbase[n]);
            cnt[n] = (unsigned)S;
        }
    }

    __threadfence_block();   // scratch stores visible to this warp's loads

    // ---------- Phase 4: exact ranking of survivors + output ----------
#pragma unroll
    for (int n = 0; n < NPW; n++) {
        const int ilocal = myBase + n;
        const int S = (int)cnt[n];
        const unsigned sb = sbase[n];
        unsigned long long* kb = skey + (size_t)wid * CAP;
        __syncwarp();
        for (int q = lane; q < S; q += 32) kb[q] = g_knn_scratch[sb + q];
        __syncwarp();
        float4 pi = spos[ilocal];
        int ig = g * M_NODES + ilocal;
        int cmax = (S + 31) >> 5;
        for (int c = 0; c < cmax; c++) {
            int o = c * 32 + lane;
            bool act = o < S;
            unsigned long long mk = act ? kb[o] : 0xFFFFFFFFFFFFFFFFull;
            int rank = 0;
#pragma unroll 4
            for (int q = 0; q < S; q++) rank += (kb[q] < mk) ? 1 : 0;   // keys unique
            if (act && rank < KNN) {
                int j = (int)(unsigned)(mk & 0xFFFFFFFFull);
                float4 pj = spos[j];
                // reference Distance transform: direct difference formula
                float dx = pj.x - pi.x, dy = pj.y - pi.y, dz = pj.z - pi.z;
                float dist = sqrtf(dx * dx + dy * dy + dz * dz);
                int jg = g * M_NODES + j;
                size_t e1 = (size_t)ig * KNN + (size_t)rank;
                size_t e2 = (size_t)NK_ + e1;
                out[e1] = (float)jg;
                out[(size_t)E_ + e1] = (float)ig;
                out[e2] = (float)ig;
                out[(size_t)E_ + e2] = (float)jg;
                out[2 * (size_t)E_ + e1] = dist;
                out[2 * (size_t)E_ + e2] = dist;
                size_t a1 = 3 * (size_t)E_ + e1 * 5;
                size_t a2 = 3 * (size_t)E_ + e2 * 5;
#pragma unroll
                for (int b = 0; b < 5; b++) {
                    float tt = dist - 2.5f * (float)b;
                    float av = expf(-((tt * tt) / 12.5f));
                    out[a1 + b] = av;
                    out[a2 + b] = av;
                }
            }
        }
        __syncwarp();
    }
}

extern "C" void kernel_launch(void* const* d_in, const int* in_sizes, int n_in,
                              void* d_out, int out_size)
{
    const float* pos = (const float*)d_in[0];   // [32768, 3] float32
    float* out = (float*)d_out;                 // [8*E_] float32 concat of outputs

    cudaFuncSetAttribute(knn_rdf_kernel,
                         cudaFuncAttributeMaxDynamicSharedMemorySize, SMEM_BYTES);
    knn_rdf_kernel<<<NBLOCKS, THREADS, SMEM_BYTES>>>(pos, out);
}

// round 3
// speedup vs baseline: 1.7382x; 1.1157x over previous
#include <cuda_runtime.h>
#include <cstdint>
#include <math.h>

// Problem constants (fixed by the dataset)
#define NUM_GRAPHS   8
#define M_NODES      4096
#define N_TOTAL      32768
#define KNN          50
#define NK_          (N_TOTAL * KNN)      // 1,638,400 directed knn edges
#define E_           (2 * NK_)            // 3,276,800 total edges
#define CAP          256                  // survivor buffer per node (incl. self)
#define NPW          8                    // nodes per warp
#define WPB          8                    // warps per block
#define NPB          (NPW * WPB)          // 64 nodes per block
#define THREADS      256
#define NBLOCKS      (N_TOTAL / NPB)      // 512
#define TARGET       85.0f                // desired survivor count (incl. self)
#define S_ITERS      12                   // 384-candidate calibration sample
#define SMEM_BYTES   (M_NODES * 16 + WPB * CAP * 8)   // 65536 + 16384 = 81920

// Global scratch for survivor keys (no cudaMalloc allowed)
__device__ unsigned long long g_knn_scratch[(size_t)N_TOTAL * CAP];

// ---- helpers ----
__device__ __forceinline__ unsigned int f2ord(float f) {
    unsigned int b = __float_as_uint(f);
    unsigned int m = ((unsigned int)((int)b >> 31)) | 0x80000000u;
    return b ^ m;
}
__device__ __forceinline__ unsigned long long pk2(float lo, float hi) {
    unsigned long long r;
    asm("mov.b64 %0, {%1,%2};" : "=l"(r) : "f"(lo), "f"(hi));
    return r;
}
__device__ __forceinline__ void upk2(float& lo, float& hi, unsigned long long v) {
    asm("mov.b64 {%0,%1}, %2;" : "=f"(lo), "=f"(hi) : "l"(v));
}
__device__ __forceinline__ unsigned long long fma2(unsigned long long a,
                                                   unsigned long long b,
                                                   unsigned long long c) {
    unsigned long long d;
    asm("fma.rn.f32x2 %0, %1, %2, %3;" : "=l"(d) : "l"(a), "l"(b), "l"(c));
    return d;
}
__device__ __forceinline__ float ex2(float x) {
    float y;
    asm("ex2.approx.f32 %0, %1;" : "=f"(y) : "f"(x));
    return y;
}

extern "C" __global__ void __launch_bounds__(THREADS, 2)
knn_rdf_kernel(const float* __restrict__ pos, float* __restrict__ out)
{
    extern __shared__ unsigned char smem_raw[];
    float4* spos = (float4*)smem_raw;                                          // [M_NODES]
    unsigned long long* skey = (unsigned long long*)(smem_raw + M_NODES * 16); // [WPB*CAP]
    __shared__ int scnt[NPB];

    const int g        = blockIdx.x / (M_NODES / NPB);
    const int chunk    = blockIdx.x % (M_NODES / NPB);
    const int nodeBase = chunk * NPB;
    const float* gp    = pos + (size_t)g * M_NODES * 3;

    // ---- load graph positions into smem as (x,y,z,|p|^2) ----
    for (int t = threadIdx.x; t < M_NODES; t += THREADS) {
        float x = gp[t * 3 + 0];
        float y = gp[t * 3 + 1];
        float z = gp[t * 3 + 2];
        spos[t] = make_float4(x, y, z, x * x + y * y + z * z);
    }
    __syncthreads();

    const int wid  = threadIdx.x >> 5;
    const int lane = threadIdx.x & 31;
    const int myBase = nodeBase + wid * NPW;
    const unsigned lmask = (1u << lane) - 1u;

    if (lane < NPW) scnt[wid * NPW + lane] = 0;
    __syncwarp();

    // per-node constants: packed (-2x,-2y,-2z) for node pairs, plus |p|^2
    float nsq[NPW];
    unsigned long long m2x[4], m2y[4], m2z[4];
#pragma unroll
    for (int k = 0; k < 4; k++) {
        float4 pa = spos[myBase + 2 * k];
        float4 pb = spos[myBase + 2 * k + 1];
        m2x[k] = pk2(-2.0f * pa.x, -2.0f * pb.x);
        m2y[k] = pk2(-2.0f * pa.y, -2.0f * pb.y);
        m2z[k] = pk2(-2.0f * pa.z, -2.0f * pb.z);
        nsq[2 * k]     = pa.w;
        nsq[2 * k + 1] = pb.w;
    }

    // ---------- Phase 1: threshold = analytic density seed + 2 count passes ----------
    // pos ~ N(0, 9 I3): count(r) ~ (4pi/3) r^3 * 9.63 e^{-rho^2/18}  =>  T = r^2 seed
    float Tn[NPW];
#pragma unroll
    for (int n = 0; n < NPW; n++) {
        float T = 1.644f * ex2(nsq[n] * 0.0534341f);   // e^{rho^2/27} as 2^{rho^2*0.05343}
        Tn[n] = fminf(fmaxf(T, 0.2f), 500.0f);
    }

#pragma unroll
    for (int pass = 0; pass < 2; pass++) {
        float Tp[NPW];
#pragma unroll
        for (int n = 0; n < NPW; n++) Tp[n] = Tn[n] - nsq[n];
        int c[NPW];
#pragma unroll
        for (int n = 0; n < NPW; n++) c[n] = 0;
        for (int s = 0; s < S_ITERS; s++) {
            float4 pj = spos[lane + s * 32];
            unsigned long long xx = pk2(pj.x, pj.x);
            unsigned long long yy = pk2(pj.y, pj.y);
            unsigned long long zz = pk2(pj.z, pj.z);
            unsigned long long ww = pk2(pj.w, pj.w);
#pragma unroll
            for (int k = 0; k < 4; k++) {
                unsigned long long a = fma2(m2x[k], xx, ww);
                a = fma2(m2y[k], yy, a);
                a = fma2(m2z[k], zz, a);
                float al, ah; upk2(al, ah, a);
                c[2 * k]     += (al <= Tp[2 * k]) ? 1 : 0;
                c[2 * k + 1] += (ah <= Tp[2 * k + 1]) ? 1 : 0;
            }
        }
#pragma unroll
        for (int n = 0; n < NPW; n++) {
            int cs = __reduce_add_sync(0xffffffffu, c[n]);
            float est = (float)cs * (4096.0f / (S_ITERS * 32.0f));
            float f = __powf(TARGET / fmaxf(est, 2.0f), 0.6666667f);
            f = fminf(fmaxf(f, 0.2f), 5.0f);
            Tn[n] *= f;
        }
    }

    // ---------- Phase 2: full scan (packed f32x2), push survivors ----------
    unsigned sbase0 = (unsigned)(g * M_NODES + myBase) * CAP;
    {
        float Tp[NPW];
#pragma unroll
        for (int n = 0; n < NPW; n++) Tp[n] = Tn[n] - nsq[n];

        for (int it = 0; it < M_NODES / 32; it++) {
            int j = lane + it * 32;
            float4 pj = spos[j];
            unsigned long long xx = pk2(pj.x, pj.x);
            unsigned long long yy = pk2(pj.y, pj.y);
            unsigned long long zz = pk2(pj.z, pj.z);
            unsigned long long ww = pk2(pj.w, pj.w);
#pragma unroll
            for (int k = 0; k < 4; k++) {
                unsigned long long a = fma2(m2x[k], xx, ww);
                a = fma2(m2y[k], yy, a);
                a = fma2(m2z[k], zz, a);
                float al, ah; upk2(al, ah, a);
                if (al <= Tp[2 * k]) {
                    int slot = atomicAdd(&scnt[wid * NPW + 2 * k], 1);
                    if (slot < CAP)
                        g_knn_scratch[sbase0 + (2 * k) * CAP + slot] =
                            ((unsigned long long)f2ord(al) << 32) | (unsigned)j;
                }
                if (ah <= Tp[2 * k + 1]) {
                    int slot = atomicAdd(&scnt[wid * NPW + 2 * k + 1], 1);
                    if (slot < CAP)
                        g_knn_scratch[sbase0 + (2 * k + 1) * CAP + slot] =
                            ((unsigned long long)f2ord(ah) << 32) | (unsigned)j;
                }
            }
        }
    }
    __syncwarp();

    unsigned cnt[NPW];
#pragma unroll
    for (int n = 0; n < NPW; n++) cnt[n] = (unsigned)scnt[wid * NPW + n];

    // ---------- Phase 3: retry (rare) — scalar count/compact with bisection ----------
    auto count_one = [&](float sx, float sy, float sz, float tp) -> int {
        int c = 0;
        for (int it = 0; it < M_NODES / 32; it++) {
            float4 pj = spos[lane + it * 32];
            float a = fmaf(sx, pj.x, pj.w);
            a = fmaf(sy, pj.y, a);
            a = fmaf(sz, pj.z, a);
            c += (a <= tp) ? 1 : 0;
        }
        return __reduce_add_sync(0xffffffffu, c);
    };
    auto compact_one = [&](float sx, float sy, float sz, float tp, unsigned sb) -> int {
        int S = 0;
        for (int it = 0; it < M_NODES / 32; it++) {
            int j = lane + it * 32;
            float4 pj = spos[j];
            float a = fmaf(sx, pj.x, pj.w);
            a = fmaf(sy, pj.y, a);
            a = fmaf(sz, pj.z, a);
            bool p = (a <= tp);
            unsigned bal = __ballot_sync(0xffffffffu, p);
            if (p) {
                int slot = S + __popc(bal & lmask);
                if (slot < CAP)
                    g_knn_scratch[sb + slot] =
                        ((unsigned long long)f2ord(a) << 32) | (unsigned)j;
            }
            S += __popc(bal);
        }
        return S;
    };

#pragma unroll
    for (int n = 0; n < NPW; n++) {
        int S = (int)cnt[n];
        if (S < KNN + 1 || S > CAP) {
            float4 pi = spos[myBase + n];
            float sx = -2.0f * pi.x, sy = -2.0f * pi.y, sz = -2.0f * pi.z;
            unsigned sb = sbase0 + n * CAP;
            float t = Tn[n] * ((S < KNN + 1) ? 1.6f : 0.6f);
            S = compact_one(sx, sy, sz, t - nsq[n], sb);
            if (S < KNN + 1 || S > CAP) {
                float lo = 0.0f, hi = 0.0f;
                bool hasHi = false;
                int c = S;
                for (int iter = 0; iter < 64 && (c < KNN + 1 || c > CAP); iter++) {
                    if (c < KNN + 1) { lo = t; t = hasHi ? 0.5f * (lo + hi) : fmaxf(t * 2.0f, 1e-6f); }
                    else             { hi = t; hasHi = true; t = 0.5f * (lo + hi); }
                    c = count_one(sx, sy, sz, t - nsq[n]);
                }
                S = compact_one(sx, sy, sz, t - nsq[n], sb);
            }
            cnt[n] = (unsigned)min(S, CAP);
        }
    }

    __threadfence_block();   // scratch stores visible across the warp's lanes

    // ---------- Phase 4: exact ranking + output ----------
#pragma unroll
    for (int n = 0; n < NPW; n++) {
        const int ilocal = myBase + n;
        const int S = (int)min(cnt[n], (unsigned)CAP);
        const unsigned sb = sbase0 + n * CAP;
        unsigned long long* kb = skey + (size_t)wid * CAP;
        __syncwarp();
        for (int q = lane; q < S; q += 32) {
            unsigned long long k = g_knn_scratch[sb + q];
            if ((unsigned)k == (unsigned)ilocal) k = 0xFFFFFFFFFFFFFFFFull; // drop self
            kb[q] = k;
        }
        __syncwarp();
        float4 pi = spos[ilocal];
        int ig = g * M_NODES + ilocal;

        for (int base = 0; base < S; base += 128) {
            unsigned long long mk[4];
            int rk[4];
#pragma unroll
            for (int c = 0; c < 4; c++) {
                int o = base + c * 32 + lane;
                mk[c] = (o < S) ? kb[o] : 0xFFFFFFFFFFFFFFFFull;
                rk[c] = 0;
            }
            // single pass over all keys; each key compared to 4 chunk candidates
            int q = 0;
            for (; q + 2 <= S; q += 2) {
                unsigned long long k0 = kb[q];
                unsigned long long k1 = kb[q + 1];
#pragma unroll
                for (int c = 0; c < 4; c++) {
                    rk[c] += (k0 < mk[c]) ? 1 : 0;
                    rk[c] += (k1 < mk[c]) ? 1 : 0;
                }
            }
            for (; q < S; q++) {
                unsigned long long k0 = kb[q];
#pragma unroll
                for (int c = 0; c < 4; c++) rk[c] += (k0 < mk[c]) ? 1 : 0;
            }
#pragma unroll
            for (int c = 0; c < 4; c++) {
                if (rk[c] < KNN) {
                    int j = (int)(unsigned)(mk[c] & 0xFFFFFFFFull);
                    float4 pj = spos[j];
                    float dx = pj.x - pi.x, dy = pj.y - pi.y, dz = pj.z - pi.z;
                    float dist = sqrtf(dx * dx + dy * dy + dz * dz);
                    int jg = g * M_NODES + j;
                    size_t e1 = (size_t)ig * KNN + (size_t)rk[c];
                    size_t e2 = (size_t)NK_ + e1;
                    out[e1] = (float)jg;
                    out[(size_t)E_ + e1] = (float)ig;
                    out[e2] = (float)ig;
                    out[(size_t)E_ + e2] = (float)jg;
                    out[2 * (size_t)E_ + e1] = dist;
                    out[2 * (size_t)E_ + e2] = dist;
                    size_t a1 = 3 * (size_t)E_ + e1 * 5;
                    size_t a2 = 3 * (size_t)E_ + e2 * 5;
#pragma unroll
                    for (int b = 0; b < 5; b++) {
                        float tt = dist - 2.5f * (float)b;
                        // exp(-t^2/12.5) = 2^(-0.11541560 * t^2)
                        float av = ex2(tt * tt * -0.11541560f);
                        out[a1 + b] = av;
                        out[a2 + b] = av;
                    }
                }
            }
        }
        __syncwarp();
    }
}

extern "C" void kernel_launch(void* const* d_in, const int* in_sizes, int n_in,
                              void* d_out, int out_size)
{
    const float* pos = (const float*)d_in[0];   // [32768, 3] float32
    float* out = (float*)d_out;                 // [8*E_] float32 concat of outputs

    cudaFuncSetAttribute(knn_rdf_kernel,
                         cudaFuncAttributeMaxDynamicSharedMemorySize, SMEM_BYTES);
    knn_rdf_kernel<<<NBLOCKS, THREADS, SMEM_BYTES>>>(pos, out);
}